// round 1
// baseline (speedup 1.0000x reference)
#include <cuda_runtime.h>
#include <cstdint>

// Problem constants
#define BD   8          // batch
#define DD   256        // embedding dim
#define HW   4096       // 64*64
#define NN   32768      // B*H*W pixels
#define KK   8192       // codebook size

// Tiling
#define PM   128        // pixels per block tile
#define KN   64         // codes per k-tile
#define KC   64         // depth (d) per chunk
#define KSPLIT 2        // split K across blockIdx.y
#define NCHUNK 256      // chunks per block: (KK/KSPLIT/KN) * (DD/KC) = 64*4

// Scratch (no cudaMalloc allowed)
__device__ float g_cbB[KK * DD * 2];   // packed, transposed, duplicated codebook (16 MB)
__device__ float g_cbsq[KK];
__device__ float g_xsq[NN];
__device__ float g_pv[KSPLIT * NN];
__device__ int   g_pk[KSPLIT * NN];

// Output layout in d_out (flat concat, reference return order)
#define OFF_ZQ1   ((size_t)0)
#define OFF_ZQ2   ((size_t)NN * DD)           // 8388608
#define OFF_LOG   ((size_t)2 * NN * DD)       // 16777216

__device__ __forceinline__ uint32_t smem_u32(const void* p) {
    uint32_t a;
    asm("{ .reg .u64 t; cvta.to.shared.u64 t, %1; cvt.u32.u64 %0, t; }" : "=r"(a) : "l"(p));
    return a;
}
__device__ __forceinline__ void cp16(uint32_t dst, const float* src) {
    asm volatile("cp.async.cg.shared.global [%0], [%1], 16;" :: "r"(dst), "l"(src));
}
#define CP_COMMIT() asm volatile("cp.async.commit_group;")
#define CP_WAIT1()  asm volatile("cp.async.wait_group 1;")
#define CP_WAIT0()  asm volatile("cp.async.wait_group 0;")

// packed fp32x2 FMA: acc = a*b + acc (pairs in 64-bit regs)
#define FMA2(accv, av, bv) \
    asm("fma.rn.f32x2 %0, %1, %2, %0;" : "+l"(accv) : "l"(av), "l"(bv))

// ---------------- prep kernels ----------------

// x_sqr per pixel. z layout [B, D, H, W] -> pixel n reads stride HW along d.
__global__ void vq_xsq(const float* __restrict__ z) {
    int n = blockIdx.x * 256 + threadIdx.x;
    int b = n >> 12, hw = n & 4095;
    const float* p = z + (size_t)b * DD * HW + hw;
    float s = 0.f;
#pragma unroll 8
    for (int d = 0; d < DD; d++) {
        float v = p[(size_t)d * HW];
        s = fmaf(v, v, s);
    }
    g_xsq[n] = s;
}

// ||c_k||^2 per code
__global__ void vq_cbsq(const float* __restrict__ cb) {
    int k = blockIdx.x * 256 + threadIdx.x;
    const float4* r = (const float4*)(cb + (size_t)k * DD);
    float s = 0.f;
#pragma unroll 8
    for (int i = 0; i < DD / 4; i++) {
        float4 v = r[i];
        s = fmaf(v.x, v.x, s); s = fmaf(v.y, v.y, s);
        s = fmaf(v.z, v.z, s); s = fmaf(v.w, v.w, s);
    }
    g_cbsq[k] = s;
}

// Pack codebook: g_cbB[chunk][d_local][2k+e] = cb[code][d]
// chunk = ktg*4 + dc; code = ktg*64 + k; d = dc*64 + d_local
__global__ void vq_pack(const float* __restrict__ cb) {
    int j = blockIdx.x * 256 + threadIdx.x;   // 0 .. 4194303
    int chunk = j >> 13;
    int rem = j & 8191;
    int d = (chunk & 3) * 64 + (rem >> 7);
    int code = (chunk >> 2) * 64 + ((rem & 127) >> 1);
    g_cbB[j] = cb[(size_t)code * DD + d];
}

// ---------------- main fused GEMM + logits + argmin ----------------
// grid (256 pixel-tiles, KSPLIT), 256 threads
// smem: As[256][128] fp32 (128KB) + 2 x Bdup[64][128] (2 x 32KB) = 192KB
__global__ void __launch_bounds__(256, 1)
vq_main(const float* __restrict__ z, float* __restrict__ out) {
    extern __shared__ float smem[];
    float* As  = smem;                  // 32768 floats
    float* Bd0 = smem + 32768;          // 8192 floats
    float* Bd1 = Bd0 + 8192;            // 8192 floats
    const int tid = threadIdx.x;
    const int tile = blockIdx.x, ks = blockIdx.y;
    const int n0 = tile * PM;
    const int b = n0 >> 12, hw0 = n0 & 4095;

    const float* cbB = g_cbB + (size_t)ks * NCHUNK * (KC * 2 * KN);
    const uint32_t bd0 = smem_u32(Bd0) + tid * 16;
    const uint32_t bd1 = smem_u32(Bd1) + tid * 16;

    // issue chunk c into buffer (c&1)
    auto issue = [&](int c) {
        const float* s = cbB + (size_t)c * 8192 + tid * 4;
        uint32_t d = (c & 1) ? bd1 : bd0;
#pragma unroll
        for (int i = 0; i < 8; i++) cp16(d + i * 4096, s + i * 1024);
        CP_COMMIT();
    };
    issue(0);

    // Load A tile (128 px x 256 d) into smem, layout As[d][px]
    {
        const float* zb = z + (size_t)b * DD * HW + hw0;
        int px = tid & 127, dr = tid >> 7;
#pragma unroll 4
        for (int i = 0; i < 128; i++) {
            int d = i * 2 + dr;
            As[d * PM + px] = zb[(size_t)d * HW + px];
        }
    }

    const int pxq = tid & 15;    // 16 pixel groups of 8 px
    const int kq  = tid >> 4;    // 16 code groups of 4 codes

    float xs[8];
    {
        float4 t0 = *(const float4*)&g_xsq[n0 + pxq * 8];
        float4 t1 = *(const float4*)&g_xsq[n0 + pxq * 8 + 4];
        xs[0]=t0.x; xs[1]=t0.y; xs[2]=t0.z; xs[3]=t0.w;
        xs[4]=t1.x; xs[5]=t1.y; xs[6]=t1.z; xs[7]=t1.w;
    }
    float bestv[8];
    int   bestk[8];
#pragma unroll
    for (int p = 0; p < 8; p++) { bestv[p] = __int_as_float(0x7f800000); bestk[p] = 0; }

    unsigned long long acc[4][4];   // [code j][px pair p]

    for (int c = 0; c < NCHUNK; c++) {
        if (c < NCHUNK - 1) { issue(c + 1); CP_WAIT1(); }
        else                { CP_WAIT0(); }
        __syncthreads();

        if ((c & 3) == 0) {
#pragma unroll
            for (int j = 0; j < 4; j++)
#pragma unroll
                for (int p = 0; p < 4; p++) acc[j][p] = 0ull;
        }

        const float* Ab = As + ((c & 3) * KC) * PM + pxq * 8;
        const float* Bb = ((c & 1) ? Bd1 : Bd0) + kq * 8;

#pragma unroll 8
        for (int dd = 0; dd < KC; dd++) {
            ulonglong2 a0 = *(const ulonglong2*)(Ab + dd * PM);
            ulonglong2 a1 = *(const ulonglong2*)(Ab + dd * PM + 4);
            ulonglong2 b0 = *(const ulonglong2*)(Bb + dd * 128);
            ulonglong2 b1 = *(const ulonglong2*)(Bb + dd * 128 + 4);
            FMA2(acc[0][0], a0.x, b0.x); FMA2(acc[0][1], a0.y, b0.x);
            FMA2(acc[0][2], a1.x, b0.x); FMA2(acc[0][3], a1.y, b0.x);
            FMA2(acc[1][0], a0.x, b0.y); FMA2(acc[1][1], a0.y, b0.y);
            FMA2(acc[1][2], a1.x, b0.y); FMA2(acc[1][3], a1.y, b0.y);
            FMA2(acc[2][0], a0.x, b1.x); FMA2(acc[2][1], a0.y, b1.x);
            FMA2(acc[2][2], a1.x, b1.x); FMA2(acc[2][3], a1.y, b1.x);
            FMA2(acc[3][0], a0.x, b1.y); FMA2(acc[3][1], a0.y, b1.y);
            FMA2(acc[3][2], a1.x, b1.y); FMA2(acc[3][3], a1.y, b1.y);
        }

        if ((c & 3) == 3) {
            // epilogue for k-tile kt = c>>2 : distances, logits store, argmin
            int kt = c >> 2;
            int kbase = ks * (KK / KSPLIT) + kt * KN + kq * 4;
            float4 cq = *(const float4*)&g_cbsq[kbase];
            float cs[4] = {cq.x, cq.y, cq.z, cq.w};
            float* lb = out + OFF_LOG + ((size_t)b * KK + kbase) * HW + hw0 + pxq * 8;
#pragma unroll
            for (int j = 0; j < 4; j++) {
                float dist[8];
#pragma unroll
                for (int p = 0; p < 4; p++) {
                    unsigned long long u = acc[j][p];
                    float lo = __uint_as_float((unsigned)(u & 0xffffffffu));
                    float hi = __uint_as_float((unsigned)(u >> 32));
                    dist[2*p]   = fmaf(-2.f, lo, cs[j] + xs[2*p]);
                    dist[2*p+1] = fmaf(-2.f, hi, cs[j] + xs[2*p+1]);
                }
                int kk = kbase + j;
#pragma unroll
                for (int p = 0; p < 8; p++) {
                    if (dist[p] < bestv[p]) { bestv[p] = dist[p]; bestk[p] = kk; }
                }
                float4 o0 = make_float4(-dist[0], -dist[1], -dist[2], -dist[3]);
                float4 o1 = make_float4(-dist[4], -dist[5], -dist[6], -dist[7]);
                *(float4*)(lb + (size_t)j * HW)     = o0;
                *(float4*)(lb + (size_t)j * HW + 4) = o1;
            }
        }
        __syncthreads();
    }

    // cross-thread argmin reduce (reuse B buffers)
    float* redv = Bd0;                 // [16][128]
    int*   redk = (int*)(Bd0 + 2048);  // [16][128]
#pragma unroll
    for (int p = 0; p < 8; p++) {
        redv[kq * PM + pxq * 8 + p] = bestv[p];
        redk[kq * PM + pxq * 8 + p] = bestk[p];
    }
    __syncthreads();
    if (tid < PM) {
        float bv = __int_as_float(0x7f800000);
        int bk = 0;
#pragma unroll
        for (int q = 0; q < 16; q++) {
            float v = redv[q * PM + tid];
            int k = redk[q * PM + tid];
            if (v < bv || (v == bv && k < bk)) { bv = v; bk = k; }
        }
        g_pv[ks * NN + n0 + tid] = bv;
        g_pk[ks * NN + n0 + tid] = bk;
    }
}

// ---------------- merge partials + gather codes ----------------
__global__ void vq_gather(const float* __restrict__ cb, float* __restrict__ out) {
    __shared__ int sidx[64];
    int n0 = blockIdx.x * 64;
    int tid = threadIdx.x;
    if (tid < 64) {
        int n = n0 + tid;
        float v0 = g_pv[n], v1 = g_pv[NN + n];
        int k0 = g_pk[n], k1 = g_pk[NN + n];
        sidx[tid] = (v1 < v0) ? k1 : k0;   // tie -> lower split (lower index)
    }
    __syncthreads();
    int px = tid & 63, dg = tid >> 6;      // 4 d-groups of 64
    int n = n0 + px;
    int b = n >> 12, hw = n & 4095;
    const float* crow = cb + (size_t)sidx[px] * DD;
    size_t obase = (size_t)b * DD * HW + hw;
#pragma unroll 8
    for (int dj = 0; dj < 64; dj++) {
        int d = dg * 64 + dj;
        float v = crow[d];
        out[OFF_ZQ1 + obase + (size_t)d * HW] = v;
        out[OFF_ZQ2 + obase + (size_t)d * HW] = v;
    }
}

extern "C" void kernel_launch(void* const* d_in, const int* in_sizes, int n_in,
                              void* d_out, int out_size) {
    const float* z  = (const float*)d_in[0];   // z_e_x [8,256,64,64]
    const float* cb = (const float*)d_in[1];   // codebook [8192,256]
    float* out = (float*)d_out;

    cudaFuncSetAttribute(vq_main, cudaFuncAttributeMaxDynamicSharedMemorySize, 196608);

    vq_xsq<<<NN / 256, 256>>>(z);
    vq_cbsq<<<KK / 256, 256>>>(cb);
    vq_pack<<<(KK * DD * 2) / 256, 256>>>(cb);
    vq_main<<<dim3(NN / PM, KSPLIT), 256, 196608>>>(z, out);
    vq_gather<<<NN / 64, 256>>>(cb, out);
}

// round 3
// speedup vs baseline: 2.3287x; 2.3287x over previous
#include <cuda_runtime.h>
#include <cstdint>

// Problem constants
#define BD   8
#define DD   256
#define HW   4096
#define NN   32768
#define KK   8192

// Tiling
#define PM   128        // pixels per block tile
#define KN   128        // codes per k-tile
#define KC   64         // depth per chunk
#define KSPLIT 4
#define NCHUNK 64       // (KK/KSPLIT/KN) * (DD/KC) = 16 * 4

// Scratch
__device__ float g_cbT[KK * DD];      // transposed chunked codebook (8 MB)
__device__ float g_cbsq[KK];
__device__ float g_xsq[NN];
__device__ float g_pv[KSPLIT * NN];
__device__ int   g_pk[KSPLIT * NN];

#define OFF_ZQ1   ((size_t)0)
#define OFF_ZQ2   ((size_t)NN * DD)
#define OFF_LOG   ((size_t)2 * NN * DD)

__device__ __forceinline__ uint32_t smem_u32(const void* p) {
    uint32_t a;
    asm("{ .reg .u64 t; cvta.to.shared.u64 t, %1; cvt.u32.u64 %0, t; }" : "=r"(a) : "l"(p));
    return a;
}
__device__ __forceinline__ void cp16(uint32_t dst, const float* src) {
    asm volatile("cp.async.cg.shared.global [%0], [%1], 16;" :: "r"(dst), "l"(src));
}
#define CP_COMMIT() asm volatile("cp.async.commit_group;")
#define CP_WAIT1()  asm volatile("cp.async.wait_group 1;")
#define CP_WAIT0()  asm volatile("cp.async.wait_group 0;")

// packed fp32x2 FMA: acc += a*b (pairs in 64-bit regs)
#define FMA2(accv, av, bv) \
    asm("fma.rn.f32x2 %0, %1, %2, %0;" : "+l"(accv) : "l"(av), "l"(bv))
// duplicate one fp32 into both halves of a 64-bit pair
#define DUP2(dst, f) \
    asm("mov.b64 %0, {%1, %1};" : "=l"(dst) : "f"(f))

// ---------------- prep kernels ----------------

__global__ void vq_xsq(const float* __restrict__ z) {
    int n = blockIdx.x * 256 + threadIdx.x;
    int b = n >> 12, hw = n & 4095;
    const float* p = z + (size_t)b * DD * HW + hw;
    float s = 0.f;
#pragma unroll 8
    for (int d = 0; d < DD; d++) {
        float v = p[(size_t)d * HW];
        s = fmaf(v, v, s);
    }
    g_xsq[n] = s;
}

__global__ void vq_cbsq(const float* __restrict__ cb) {
    int k = blockIdx.x * 256 + threadIdx.x;
    const float4* r = (const float4*)(cb + (size_t)k * DD);
    float s = 0.f;
#pragma unroll 8
    for (int i = 0; i < DD / 4; i++) {
        float4 v = r[i];
        s = fmaf(v.x, v.x, s); s = fmaf(v.y, v.y, s);
        s = fmaf(v.z, v.z, s); s = fmaf(v.w, v.w, s);
    }
    g_cbsq[k] = s;
}

// g_cbT layout: [chunk(256)][d_local(64)][code_in_tile(128)]
// chunk = ktile*4 + dc ; code = ktile*128 + k ; d = dc*64 + d_local
__global__ void vq_pack(const float* __restrict__ cb) {
    int j = blockIdx.x * 256 + threadIdx.x;   // 0 .. 2097151
    int chunk = j >> 13;
    int rem = j & 8191;
    int d = (chunk & 3) * 64 + (rem >> 7);
    int code = (chunk >> 2) * 128 + (rem & 127);
    g_cbT[j] = cb[(size_t)code * DD + d];
}

// ---------------- main fused GEMM + logits + argmin ----------------
// grid (256, KSPLIT), 256 threads
// smem: As[256][128] (128KB) + 2 x B[64][128] (2 x 32KB) = 192KB
__global__ void __launch_bounds__(256, 1)
vq_main(const float* __restrict__ z, float* __restrict__ out) {
    extern __shared__ float smem[];
    float* As  = smem;                  // 32768 floats
    float* Bd0 = smem + 32768;          // 8192 floats
    float* Bd1 = Bd0 + 8192;
    const int tid = threadIdx.x;
    const int tile = blockIdx.x, ks = blockIdx.y;
    const int n0 = tile * PM;
    const int b = n0 >> 12, hw0 = n0 & 4095;

    const float* cbB = g_cbT + (size_t)ks * NCHUNK * 8192;
    const uint32_t bd0 = smem_u32(Bd0) + tid * 16;
    const uint32_t bd1 = smem_u32(Bd1) + tid * 16;

    auto issue = [&](int c) {
        const float* s = cbB + (size_t)c * 8192 + tid * 4;
        uint32_t d = (c & 1) ? bd1 : bd0;
#pragma unroll
        for (int i = 0; i < 8; i++) cp16(d + i * 4096, s + i * 1024);
        CP_COMMIT();
    };

    // A tile via cp.async: 256d x 128px x 4B = 8192 x 16B chunks, 32 per thread
    {
        const float* zb = z + (size_t)b * DD * HW + hw0;
        uint32_t aBase = smem_u32(As);
#pragma unroll
        for (int i = 0; i < 32; i++) {
            int c = tid + i * 256;
            int d = c >> 5, p4 = (c & 31) * 4;
            cp16(aBase + c * 16, zb + (size_t)d * HW + p4);
        }
    }
    issue(0);   // commits A + B0 as group 0

    const int pxq = tid & 15;    // 16 pixel groups
    const int kq  = tid >> 4;    // 16 code groups of 8 codes
    const int px0 = 4 * pxq;     // pixels px0..px0+3 and 64+px0..64+px0+3

    float xs[8];
    {
        float4 t0 = *(const float4*)&g_xsq[n0 + px0];
        float4 t1 = *(const float4*)&g_xsq[n0 + 64 + px0];
        xs[0]=t0.x; xs[1]=t0.y; xs[2]=t0.z; xs[3]=t0.w;
        xs[4]=t1.x; xs[5]=t1.y; xs[6]=t1.z; xs[7]=t1.w;
    }
    float bestv[8];
    int   bestk[8];
#pragma unroll
    for (int p = 0; p < 8; p++) { bestv[p] = __int_as_float(0x7f800000); bestk[p] = 0; }

    unsigned long long acc[8][4];   // [code j][px pair]

    for (int c = 0; c < NCHUNK; c++) {
        if (c < NCHUNK - 1) { issue(c + 1); CP_WAIT1(); }
        else                { CP_WAIT0(); }
        __syncthreads();

        if ((c & 3) == 0) {
#pragma unroll
            for (int j = 0; j < 8; j++)
#pragma unroll
                for (int p = 0; p < 4; p++) acc[j][p] = 0ull;
        }

        const float* Ab = As + ((c & 3) * KC) * PM + px0;
        const float* Bb = ((c & 1) ? Bd1 : Bd0) + kq * 8;

#pragma unroll 8
        for (int dd = 0; dd < KC; dd++) {
            ulonglong2 a0 = *(const ulonglong2*)(Ab + dd * PM);
            ulonglong2 a1 = *(const ulonglong2*)(Ab + dd * PM + 64);
            float4 bf0 = *(const float4*)(Bb + dd * KN);
            float4 bf1 = *(const float4*)(Bb + dd * KN + 4);
            unsigned long long bp0, bp1, bp2, bp3, bp4, bp5, bp6, bp7;
            DUP2(bp0, bf0.x); DUP2(bp1, bf0.y); DUP2(bp2, bf0.z); DUP2(bp3, bf0.w);
            DUP2(bp4, bf1.x); DUP2(bp5, bf1.y); DUP2(bp6, bf1.z); DUP2(bp7, bf1.w);
            FMA2(acc[0][0], a0.x, bp0); FMA2(acc[0][1], a0.y, bp0);
            FMA2(acc[0][2], a1.x, bp0); FMA2(acc[0][3], a1.y, bp0);
            FMA2(acc[1][0], a0.x, bp1); FMA2(acc[1][1], a0.y, bp1);
            FMA2(acc[1][2], a1.x, bp1); FMA2(acc[1][3], a1.y, bp1);
            FMA2(acc[2][0], a0.x, bp2); FMA2(acc[2][1], a0.y, bp2);
            FMA2(acc[2][2], a1.x, bp2); FMA2(acc[2][3], a1.y, bp2);
            FMA2(acc[3][0], a0.x, bp3); FMA2(acc[3][1], a0.y, bp3);
            FMA2(acc[3][2], a1.x, bp3); FMA2(acc[3][3], a1.y, bp3);
            FMA2(acc[4][0], a0.x, bp4); FMA2(acc[4][1], a0.y, bp4);
            FMA2(acc[4][2], a1.x, bp4); FMA2(acc[4][3], a1.y, bp4);
            FMA2(acc[5][0], a0.x, bp5); FMA2(acc[5][1], a0.y, bp5);
            FMA2(acc[5][2], a1.x, bp5); FMA2(acc[5][3], a1.y, bp5);
            FMA2(acc[6][0], a0.x, bp6); FMA2(acc[6][1], a0.y, bp6);
            FMA2(acc[6][2], a1.x, bp6); FMA2(acc[6][3], a1.y, bp6);
            FMA2(acc[7][0], a0.x, bp7); FMA2(acc[7][1], a0.y, bp7);
            FMA2(acc[7][2], a1.x, bp7); FMA2(acc[7][3], a1.y, bp7);
        }

        if ((c & 3) == 3) {
            int kt = c >> 2;
            int kbase = ks * (KK / KSPLIT) + kt * KN + kq * 8;
            float4 cq0 = *(const float4*)&g_cbsq[kbase];
            float4 cq1 = *(const float4*)&g_cbsq[kbase + 4];
            float cs[8] = {cq0.x, cq0.y, cq0.z, cq0.w, cq1.x, cq1.y, cq1.z, cq1.w};
            float* lb = out + OFF_LOG + ((size_t)b * KK + kbase) * HW + hw0 + px0;
#pragma unroll
            for (int j = 0; j < 8; j++) {
                float dist[8];
#pragma unroll
                for (int p = 0; p < 4; p++) {
                    unsigned long long u = acc[j][p];
                    float lo = __uint_as_float((unsigned)(u & 0xffffffffu));
                    float hi = __uint_as_float((unsigned)(u >> 32));
                    dist[2*p]   = fmaf(-2.f, lo, cs[j] + xs[2*p]);
                    dist[2*p+1] = fmaf(-2.f, hi, cs[j] + xs[2*p+1]);
                }
                int kk = kbase + j;
#pragma unroll
                for (int p = 0; p < 8; p++) {
                    if (dist[p] < bestv[p]) { bestv[p] = dist[p]; bestk[p] = kk; }
                }
                *(float4*)(lb + (size_t)j * HW) =
                    make_float4(-dist[0], -dist[1], -dist[2], -dist[3]);
                *(float4*)(lb + (size_t)j * HW + 64) =
                    make_float4(-dist[4], -dist[5], -dist[6], -dist[7]);
            }
        }
        __syncthreads();
    }

    // cross-thread argmin reduce (reuse B buffer)
    float* redv = Bd0;                 // [16][128]
    int*   redk = (int*)(Bd0 + 2048);
#pragma unroll
    for (int p = 0; p < 4; p++) {
        redv[kq * PM + px0 + p] = bestv[p];
        redk[kq * PM + px0 + p] = bestk[p];
        redv[kq * PM + 64 + px0 + p] = bestv[4 + p];
        redk[kq * PM + 64 + px0 + p] = bestk[4 + p];
    }
    __syncthreads();
    if (tid < PM) {
        float bv = __int_as_float(0x7f800000);
        int bk = 0;
#pragma unroll
        for (int q = 0; q < 16; q++) {
            float v = redv[q * PM + tid];
            int k = redk[q * PM + tid];
            if (v < bv || (v == bv && k < bk)) { bv = v; bk = k; }
        }
        g_pv[ks * NN + n0 + tid] = bv;
        g_pk[ks * NN + n0 + tid] = bk;
    }
}

// ---------------- merge partials + gather codes ----------------
__global__ void vq_gather(const float* __restrict__ cb, float* __restrict__ out) {
    __shared__ int sidx[64];
    int n0 = blockIdx.x * 64;
    int tid = threadIdx.x;
    if (tid < 64) {
        int n = n0 + tid;
        float bv = g_pv[n]; int bk = g_pk[n];
#pragma unroll
        for (int s = 1; s < KSPLIT; s++) {
            float v = g_pv[s * NN + n];
            int k = g_pk[s * NN + n];
            if (v < bv) { bv = v; bk = k; }   // splits ascending in k: strict < keeps lowest
        }
        sidx[tid] = bk;
    }
    __syncthreads();
    int px = tid & 63, dg = tid >> 6;
    int n = n0 + px;
    int b = n >> 12, hw = n & 4095;
    const float* crow = cb + (size_t)sidx[px] * DD;
    size_t obase = (size_t)b * DD * HW + hw;
#pragma unroll 8
    for (int dj = 0; dj < 64; dj++) {
        int d = dg * 64 + dj;
        float v = crow[d];
        out[OFF_ZQ1 + obase + (size_t)d * HW] = v;
        out[OFF_ZQ2 + obase + (size_t)d * HW] = v;
    }
}

extern "C" void kernel_launch(void* const* d_in, const int* in_sizes, int n_in,
                              void* d_out, int out_size) {
    const float* z  = (const float*)d_in[0];
    const float* cb = (const float*)d_in[1];
    float* out = (float*)d_out;

    cudaFuncSetAttribute(vq_main, cudaFuncAttributeMaxDynamicSharedMemorySize, 196608);

    vq_xsq<<<NN / 256, 256>>>(z);
    vq_cbsq<<<KK / 256, 256>>>(cb);
    vq_pack<<<(KK * DD) / 256, 256>>>(cb);
    vq_main<<<dim3(NN / PM, KSPLIT), 256, 196608>>>(z, out);
    vq_gather<<<NN / 64, 256>>>(cb, out);
}